// round 15
// baseline (speedup 1.0000x reference)
#include <cuda_runtime.h>
#include <cuda_fp16.h>
#include <math.h>

// Problem constants
#define Bn 8
#define Ln 4096
#define Hn 1024
#define Nn 32
#define Tn 128            // chunk length
#define Cc 32             // chunks (Tn*Cc == Ln)
#define BC 256            // B*C columns

// ---- persistent device buffers (no allocs allowed) ----
__device__ __align__(256) __half  g_V[(size_t)Hn * BC * 128];   // per-h u operand [256][128]
__device__ __align__(256) __half  g_yT16[(size_t)Hn * BC * Tn]; // per-h output [256][128] fp16
__device__ __align__(256) __half  g_Enc[(size_t)Hn * 64 * 128]; // per-h Enc [64][128]
__device__ __align__(256) __half  g_Dec[(size_t)Hn * 128 * 64]; // per-h Dec [128][64]
__device__ __align__(256) float   g_Ks[Hn * 128];               // per-h kernel taps
__device__ __align__(256) float2  g_wT[Hn * Nn];                // w^128 per (h,n)

// ---- small helpers ----
static __device__ __forceinline__ unsigned smem_u32(const void* p) {
    unsigned r;
    asm("{ .reg .u64 t; cvta.to.shared.u64 t, %1; cvt.u32.u64 %0, t; }"
        : "=r"(r) : "l"(p));
    return r;
}
static __device__ __forceinline__ void cp16(unsigned dst, const void* src) {
    asm volatile("cp.async.cg.shared.global [%0], [%1], 16;" :: "r"(dst), "l"(src));
}
static __device__ __forceinline__ void cp_commit() {
    asm volatile("cp.async.commit_group;");
}
static __device__ __forceinline__ void cp_wait_all() {
    asm volatile("cp.async.wait_group 0;");
}
static __device__ __forceinline__ void ldmA(unsigned addr, unsigned& r0, unsigned& r1,
                                            unsigned& r2, unsigned& r3) {
    asm volatile("ldmatrix.sync.aligned.m8n8.x4.shared.b16 {%0,%1,%2,%3}, [%4];"
                 : "=r"(r0), "=r"(r1), "=r"(r2), "=r"(r3) : "r"(addr));
}
static __device__ __forceinline__ void ldmB(unsigned addr, unsigned& r0, unsigned& r1) {
    asm volatile("ldmatrix.sync.aligned.m8n8.x2.shared.b16 {%0,%1}, [%2];"
                 : "=r"(r0), "=r"(r1) : "r"(addr));
}
static __device__ __forceinline__ void mma16816(float* d, const unsigned* a,
                                                const unsigned* b) {
    asm volatile(
        "mma.sync.aligned.m16n8k16.row.col.f32.f16.f16.f32 "
        "{%0,%1,%2,%3}, {%4,%5,%6,%7}, {%8,%9}, {%0,%1,%2,%3};"
        : "+f"(d[0]), "+f"(d[1]), "+f"(d[2]), "+f"(d[3])
        : "r"(a[0]), "r"(a[1]), "r"(a[2]), "r"(a[3]), "r"(b[0]), "r"(b[1]));
}

// Fast branch-free erf-GELU (A&S 7.1.26, |eps_erf| < 1.5e-7)
static __device__ __forceinline__ float gelu_erf(float v) {
    float z = fabsf(v) * 0.70710678118654752440f;
    float t = __fdividef(1.0f, fmaf(0.3275911f, z, 1.0f));
    float p = fmaf(1.061405429f, t, -1.453152027f);
    p = fmaf(p, t, 1.421413741f);
    p = fmaf(p, t, -0.284496736f);
    p = fmaf(p, t, 0.254829592f);
    p *= t;
    float e = __expf(-z * z);
    float erfz = fmaf(-p, e, 1.0f);
    float erfv = copysignf(erfz, v);
    return 0.5f * v * (1.0f + erfv);
}

// =====================================================================
// k_tables (parallel): per-h Enc/Dec/Ks/wT via direct w^s evaluation
// =====================================================================
#define LDE 136
__global__ void __launch_bounds__(256)
k_tables(const float* __restrict__ log_dt, const float* __restrict__ A_real,
         const float* __restrict__ A_imag, const float* __restrict__ C_real,
         const float* __restrict__ C_imag) {
    int h = blockIdx.x;
    int tid = threadIdx.x;
    __shared__ float s_ar[32], s_ai[32], s_cr[32], s_ci[32];
    __shared__ __half encS[64 * LDE];

    if (tid < 32) {
        int n = tid, idx = h * Nn + n;
        float dt = expf(log_dt[h]);
        float Ar = -expf(A_real[idx]);
        float Ai = A_imag[idx];
        float ar = Ar * dt, ai = Ai * dt;
        float er = expf(ar);
        float sn, cs;
        sincosf(ai, &sn, &cs);
        float wr = er * cs, wi = er * sn;
        float den = Ar * Ar + Ai * Ai;
        float e1r = wr - 1.0f, e1i = wi;
        float qr = (e1r * Ar + e1i * Ai) / den;
        float qi = (e1i * Ar - e1r * Ai) / den;
        float Cr = C_real[idx], Ci = C_imag[idx];
        s_ar[n] = ar; s_ai[n] = ai;
        s_cr[n] = Cr * qr - Ci * qi;
        s_ci[n] = Cr * qi + Ci * qr;
        float erT = expf(128.f * ar);
        float snT, csT;
        sincosf(128.f * ai, &snT, &csT);
        g_wT[h * Nn + n] = make_float2(erT * csT, erT * snT);
    }
    __syncthreads();

    int n = tid & 31, w = tid >> 5;
#pragma unroll
    for (int q = 0; q < 16; q++) {
        int s = w * 16 + q;
        float ar = s_ar[n], ai = s_ai[n];
        float fs = (float)s;
        float er = __expf(fs * ar);
        float sn, cs;
        sincosf(fs * ai, &sn, &cs);
        float wr = er * cs, wi = er * sn;          // w^s
        encS[n * LDE + (127 - s)]        = __float2half(wr);
        encS[(n + 32) * LDE + (127 - s)] = __float2half(wi);

        float er1 = __expf((fs + 1.f) * ar);
        float sn1, cs1;
        sincosf((fs + 1.f) * ai, &sn1, &cs1);
        float pr = er1 * cs1, pi = er1 * sn1;      // w^{s+1}
        float cr = s_cr[n], ci = s_ci[n];
        float dr = cr * pr - ci * pi, di = cr * pi + ci * pr;
        __half* dec = g_Dec + (size_t)h * 128 * 64 + s * 64;
        dec[n]      = __float2half(2.0f * dr);
        dec[32 + n] = __float2half(-2.0f * di);

        float term = 2.0f * (cr * wr - ci * wi);
#pragma unroll
        for (int off = 16; off; off >>= 1)
            term += __shfl_xor_sync(0xffffffffu, term, off);
        if (n == 0) g_Ks[h * 128 + s] = term;
    }
    __syncthreads();
    {
        uint4* dst = reinterpret_cast<uint4*>(g_Enc + (size_t)h * 64 * 128);
        for (int i = tid; i < 64 * 16; i += 256) {
            int row = i >> 4, ch = i & 15;
            dst[i] = *reinterpret_cast<const uint4*>(&encS[row * LDE + ch * 8]);
        }
    }
}

// =====================================================================
// k_transpose: u (b,l,h) fp32 -> g_V[h][bc][0..128) fp16
// =====================================================================
__global__ void __launch_bounds__(256)
k_transpose(const float* __restrict__ u) {
    int ht = blockIdx.x, c = blockIdx.y, b = blockIdx.z;
    __shared__ __half ts[32][136];
    int lane = threadIdx.x & 31;
    int r = threadIdx.x >> 5;

    const float* up = u + ((size_t)b * Ln + (size_t)c * Tn) * Hn + ht * 32;
#pragma unroll
    for (int j0 = 0; j0 < Tn; j0 += 8) {
        int j = j0 + r;
        ts[lane][j] = __float2half(up[(size_t)j * Hn + lane]);
    }
    __syncthreads();

    int row = threadIdx.x >> 3;
    int ch = threadIdx.x & 7;
    int bc = b * Cc + c;
    __half* dst = g_V + ((size_t)(ht * 32 + row) * BC + bc) * 128;
    reinterpret_cast<uint4*>(dst)[ch] =
        *reinterpret_cast<const uint4*>(&ts[row][ch * 8]);
    reinterpret_cast<uint4*>(dst)[ch + 8] =
        *reinterpret_cast<const uint4*>(&ts[row][(ch + 8) * 8]);
}

// =====================================================================
// k_fused: one block per (h, bc-quarter q). 64 bc columns = 2 batches.
//   p1: cp.async u-tile -> Bs cols 0..127; Enc -> R1; Ksh LDG
//   p2: encode GEMM Xl[64,64] = Enc @ Bu^T
//   p3: Xl -> R1 (fp32); prefetch Dec (R1+DEC_OFF); combine -> states
//   p4: Dec GEMM (K=64) into acc
//   p5: Toeplitz build (R1 base) ; Toep GEMM (K=128, triangular skip)
//   p6: epilogue staging -> g_yT16
// smem 61.4KB -> 3 CTAs/SM.
// =====================================================================
#define LDB  200
#define LDA1 136   // Enc stride
#define LDXf 66    // Xl fp32 stride
#define LDA  136   // Toeplitz stride
#define LDD  72    // Dec stride
#define LDO  136
#define DEC_OFF 16896                      // bytes within R1 (after Xl)
#define R1_BYTES 35840
#define SMEM_FUSED (64 * LDB * 2 + R1_BYTES)   // 61440

__global__ void __launch_bounds__(256, 3)
k_fused() {
    int h = blockIdx.x;
    int q = blockIdx.y;
    int tid = threadIdx.x;
    extern __shared__ __half sm[];
    __half* Bs = sm;                       // [64][LDB]
    char* R1 = (char*)(sm + 64 * LDB);     // 35840B scratch
    __shared__ float Ksh[128];
    unsigned bsA = smem_u32(Bs), r1A = smem_u32(R1);

    // ---- p1: async loads ----
    {
        const __half* vb = g_V + ((size_t)h * BC + q * 64) * 128;
        for (int i = tid; i < 64 * 16; i += 256) {
            int row = i >> 4, ch = i & 15;
            cp16(bsA + (unsigned)((row * LDB + ch * 8) * 2),
                 vb + (size_t)row * 128 + ch * 8);
        }
        const __half* eg = g_Enc + (size_t)h * 64 * 128;
        for (int i = tid; i < 64 * 16; i += 256) {
            int row = i >> 4, ch = i & 15;
            cp16(r1A + (unsigned)((row * LDA1 + ch * 8) * 2),
                 eg + (size_t)row * 128 + ch * 8);
        }
        cp_commit();
    }
    if (tid < 128) Ksh[tid] = g_Ks[h * 128 + tid];
    cp_wait_all();
    __syncthreads();

    int wid = tid >> 5, lane = tid & 31;
    int la = lane & 15;
    int aRowOff = (lane < 16) ? lane : (lane - 16);
    int aColOff = (lane < 16) ? 0 : 8;
    int bRowOff = la & 7;
    int bColOff = (la >> 3) * 8;

    // ---- p2: encode GEMM  Xl[64,64] = Enc[64,128] @ Bu[64,128]^T ----
    {
        int m_base = (wid & 3) * 16, n_base = (wid >> 2) * 32;
        float accE[4][4];
#pragma unroll
        for (int bI = 0; bI < 4; bI++)
#pragma unroll
            for (int cI = 0; cI < 4; cI++) accE[bI][cI] = 0.f;

        unsigned eaB = r1A + (unsigned)(((m_base + aRowOff) * LDA1 + aColOff) * 2);
        unsigned ebB = bsA + (unsigned)(((n_base + bRowOff) * LDB + bColOff) * 2);
        unsigned af[2][4];
        unsigned bf[2][4][2];

#define LOAD_E(buf, ks_)                                                      \
    {                                                                         \
        const int kk_ = (ks_) * 16;                                           \
        ldmA(eaB + (unsigned)(kk_ * 2), af[buf][0], af[buf][1],               \
             af[buf][2], af[buf][3]);                                         \
        _Pragma("unroll")                                                     \
        for (int nf = 0; nf < 4; nf++)                                        \
            ldmB(ebB + (unsigned)((nf * 8 * LDB + kk_) * 2),                  \
                 bf[buf][nf][0], bf[buf][nf][1]);                             \
    }
        LOAD_E(0, 0)
#pragma unroll
        for (int it = 0; it < 8; it++) {
            int cur = it & 1;
            if (it < 7) LOAD_E(cur ^ 1, it + 1)
#pragma unroll
            for (int nf = 0; nf < 4; nf++)
                mma16816(accE[nf], af[cur], bf[cur][nf]);
        }
#undef LOAD_E
        __syncthreads();   // Enc reads done -> reuse R1 as Xl

        float* Xls = reinterpret_cast<float*>(R1);
        int r = lane >> 2, cp = lane & 3;
#pragma unroll
        for (int nf = 0; nf < 4; nf++) {
            int m = m_base + r;
            int nn = n_base + nf * 8 + cp * 2;
            *reinterpret_cast<float2*>(&Xls[m * LDXf + nn]) =
                make_float2(accE[nf][0], accE[nf][1]);
            *reinterpret_cast<float2*>(&Xls[(m + 8) * LDXf + nn]) =
                make_float2(accE[nf][2], accE[nf][3]);
        }
    }
    __syncthreads();

    // ---- p3: Dec prefetch (R1+DEC_OFF, no overlap with Xl) + combine ----
    {
        const __half* dg = g_Dec + (size_t)h * 128 * 64;
        for (int i = tid; i < 128 * 8; i += 256) {
            int row = i >> 3, ch = i & 7;
            cp16(r1A + DEC_OFF + (unsigned)(row * LDD * 2 + ch * 16),
                 dg + (size_t)row * 64 + ch * 8);
        }
        cp_commit();
    }
    if (tid < 64) {
        const float* Xls = reinterpret_cast<const float*>(R1);
        int n = tid & 31, bl = tid >> 5;          // local batch 0..1
        float2 wT = g_wT[h * Nn + n];
        float XR = 0.f, XI = 0.f;
        const float* xR = &Xls[n * LDXf];
        const float* xI = &Xls[(n + 32) * LDXf];
#pragma unroll 4
        for (int c = 0; c < Cc; c++) {
            int bcL = bl * Cc + c;                // local row 0..63
            Bs[bcL * LDB + 128 + n] = __float2half(XR);
            Bs[bcL * LDB + 160 + n] = __float2half(XI);
            float lr = xR[bcL], li = xI[bcL];
            float nR = wT.x * XR - wT.y * XI + lr;
            float nI = wT.x * XI + wT.y * XR + li;
            XR = nR; XI = nI;
        }
    }
    cp_wait_all();
    __syncthreads();

    // main warp tiling: m 4x32, n 2x32; SMSP-balanced short/long
    int m_idx = (wid < 4) ? (wid & 1) : (2 + (wid & 1));
    int n_idx = (wid >> 1) & 1;
    int m_base = m_idx * 32, n_base = n_idx * 32;

    float acc[2][4][4];
#pragma unroll
    for (int a = 0; a < 2; a++)
#pragma unroll
        for (int bI = 0; bI < 4; bI++)
#pragma unroll
            for (int cI = 0; cI < 4; cI++) acc[a][bI][cI] = 0.f;

    unsigned af[2][2][4];
    unsigned bf[2][4][2];

#define LOAD_AB(buf, aB_, lda_, bB_, ks_)                                     \
    {                                                                         \
        const int kk_ = (ks_) * 16;                                           \
        _Pragma("unroll")                                                     \
        for (int mf = 0; mf < 2; mf++)                                        \
            ldmA((aB_) + (unsigned)((mf * 16 * (lda_) + kk_) * 2),            \
                 af[buf][mf][0], af[buf][mf][1], af[buf][mf][2], af[buf][mf][3]); \
        _Pragma("unroll")                                                     \
        for (int nf = 0; nf < 4; nf++)                                        \
            ldmB((bB_) + (unsigned)((nf * 8 * LDB + kk_) * 2),                \
                 bf[buf][nf][0], bf[buf][nf][1]);                             \
    }
#define MMA_STEP(buf)                                                         \
    {                                                                         \
        _Pragma("unroll")                                                     \
        for (int mf = 0; mf < 2; mf++)                                        \
            _Pragma("unroll")                                                 \
            for (int nf = 0; nf < 4; nf++)                                    \
                mma16816(acc[mf][nf], af[buf][mf], bf[buf][nf]);              \
    }

    // ---- p4: Dec GEMM (K=64) ----
    {
        unsigned aB = r1A + DEC_OFF +
                      (unsigned)(((m_base + aRowOff) * LDD + aColOff) * 2);
        unsigned bB = bsA +
                      (unsigned)(((n_base + bRowOff) * LDB + 128 + bColOff) * 2);
        LOAD_AB(0, aB, LDD, bB, 0)
#pragma unroll
        for (int it = 0; it < 4; it++) {
            int cur = it & 1;
            if (it < 3) LOAD_AB(cur ^ 1, aB, LDD, bB, it + 1)
            MMA_STEP(cur)
        }
    }
    __syncthreads();   // Dec reads done -> build Toeplitz over R1 base

    // ---- p5a: Toeplitz build ----
    {
        __half* As = reinterpret_cast<__half*>(R1);
        for (int i = tid; i < 128 * 16; i += 256) {
            int row = i >> 4, ch = i & 15;
            int j0 = ch * 8;
            __half hv[8];
#pragma unroll
            for (int k = 0; k < 8; k++) {
                int j = j0 + k;
                hv[k] = __float2half((row >= j) ? Ksh[row - j] : 0.f);
            }
            *reinterpret_cast<uint4*>(&As[row * LDA + j0]) =
                *reinterpret_cast<const uint4*>(hv);
        }
    }
    __syncthreads();

    // ---- p5b: Toeplitz GEMM (K=128, triangular skip for m<64) ----
    {
        unsigned aB = r1A + (unsigned)(((m_base + aRowOff) * LDA + aColOff) * 2);
        unsigned bB = bsA + (unsigned)(((n_base + bRowOff) * LDB + bColOff) * 2);
        if (m_idx < 2) {
            LOAD_AB(0, aB, LDA, bB, 0)
#pragma unroll
            for (int it = 0; it < 4; it++) {
                int cur = it & 1;
                if (it < 3) LOAD_AB(cur ^ 1, aB, LDA, bB, it + 1)
                MMA_STEP(cur)
            }
        } else {
            LOAD_AB(0, aB, LDA, bB, 0)
#pragma unroll
            for (int it = 0; it < 8; it++) {
                int cur = it & 1;
                if (it < 7) LOAD_AB(cur ^ 1, aB, LDA, bB, it + 1)
                MMA_STEP(cur)
            }
        }
    }
#undef LOAD_AB
#undef MMA_STEP

    // ---- p6: epilogue staging + coalesced store ----
    __syncthreads();
    __half* ot = reinterpret_cast<__half*>(R1);   // [64 bc][LDO]
    {
        int r = lane >> 2, cp = lane & 3;
#pragma unroll
        for (int mf = 0; mf < 2; mf++) {
            int m = m_base + mf * 16 + r;
#pragma unroll
            for (int nf = 0; nf < 4; nf++) {
                int nn = n_base + nf * 8 + cp * 2;
                ot[nn * LDO + m]           = __float2half(acc[mf][nf][0]);
                ot[(nn + 1) * LDO + m]     = __float2half(acc[mf][nf][1]);
                ot[nn * LDO + m + 8]       = __float2half(acc[mf][nf][2]);
                ot[(nn + 1) * LDO + m + 8] = __float2half(acc[mf][nf][3]);
            }
        }
    }
    __syncthreads();
    {
        __half* dst = g_yT16 + ((size_t)h * BC + q * 64) * Tn;
        for (int i = tid; i < 64 * 16; i += 256) {
            int row = i >> 4, ch = i & 15;
            *reinterpret_cast<uint4*>(&dst[row * Tn + ch * 8]) =
                *reinterpret_cast<const uint4*>(&ot[row * LDO + ch * 8]);
        }
    }
}

// =====================================================================
// k_final: transpose yT16 -> (b,l,h), + D*u (skipped when D==0), GELU
// =====================================================================
__global__ void __launch_bounds__(256)
k_final(const float* __restrict__ u, const float* __restrict__ Dp,
        float* __restrict__ out) {
    int ht = blockIdx.x, c = blockIdx.y, b = blockIdx.z;
    __shared__ float ys[128][33];
    int bc = b * Cc + c;

    {
#pragma unroll
        for (int qq = 0; qq < 2; qq++) {
            int idx = threadIdx.x + qq * 256;
            int row = idx >> 4;
            int ch = idx & 15;
            const uint4* src = reinterpret_cast<const uint4*>(
                g_yT16 + ((size_t)(ht * 32 + row) * BC + bc) * Tn);
            uint4 v = src[ch];
            const __half* hp = reinterpret_cast<const __half*>(&v);
            int i = ch * 8;
#pragma unroll
            for (int k = 0; k < 8; k++)
                ys[i + k][row] = __half2float(hp[k]);
        }
    }
    __syncthreads();

    float Dv = *Dp;
    int lane = threadIdx.x & 31;
    int r = threadIdx.x >> 5;
    size_t base = ((size_t)b * Ln + (size_t)c * Tn + r) * Hn + ht * 32 + lane;
    if (Dv != 0.0f) {
#pragma unroll
        for (int i0 = 0; i0 < Tn; i0 += 8) {
            int i = i0 + r;
            size_t gidx = base + (size_t)i0 * Hn;
            out[gidx] = gelu_erf(ys[i][lane] + Dv * u[gidx]);
        }
    } else {
#pragma unroll
        for (int i0 = 0; i0 < Tn; i0 += 8) {
            int i = i0 + r;
            size_t gidx = base + (size_t)i0 * Hn;
            out[gidx] = gelu_erf(ys[i][lane]);
        }
    }
}

// =====================================================================
// launch: single stream  tables -> transpose -> fused -> final
// =====================================================================
extern "C" void kernel_launch(void* const* d_in, const int* in_sizes, int n_in,
                              void* d_out, int out_size) {
    (void)in_sizes; (void)n_in; (void)out_size;
    const float* u      = (const float*)d_in[0];
    const float* log_dt = (const float*)d_in[1];
    const float* A_real = (const float*)d_in[2];
    const float* A_imag = (const float*)d_in[3];
    const float* C_real = (const float*)d_in[4];
    const float* C_imag = (const float*)d_in[5];
    const float* D      = (const float*)d_in[6];
    float* out = (float*)d_out;

    static bool init_done = false;
    if (!init_done) {
        cudaFuncSetAttribute(k_fused, cudaFuncAttributeMaxDynamicSharedMemorySize,
                             SMEM_FUSED);
        init_done = true;
    }

    k_tables<<<Hn, 256>>>(log_dt, A_real, A_imag, C_real, C_imag);
    k_transpose<<<dim3(Hn / 32, Cc, Bn), 256>>>(u);
    k_fused<<<dim3(Hn, 4), 256, SMEM_FUSED>>>();
    k_final<<<dim3(Hn / 32, Cc, Bn), 256>>>(u, D, out);
}

// round 16
// speedup vs baseline: 1.1577x; 1.1577x over previous
#include <cuda_runtime.h>
#include <cuda_fp16.h>
#include <math.h>

// Problem constants
#define Bn 8
#define Ln 4096
#define Hn 1024
#define Nn 32
#define Tn 128            // chunk length
#define Cc 32             // chunks (Tn*Cc == Ln)
#define BC 256            // B*C columns
#define KD 192            // main GEMM K dim: 128 (u) + 64 (states)

// ---- persistent device buffers (no allocs allowed) ----
__device__ __align__(256) __half  g_V[(size_t)Hn * BC * 128];  // per-h u operand [256][128]
__device__ __align__(256) __half  g_yT16[(size_t)Hn * BC * Tn];// per-h output [256][128] fp16

// ---- small helpers ----
static __device__ __forceinline__ unsigned smem_u32(const void* p) {
    unsigned r;
    asm("{ .reg .u64 t; cvta.to.shared.u64 t, %1; cvt.u32.u64 %0, t; }"
        : "=r"(r) : "l"(p));
    return r;
}
static __device__ __forceinline__ void cp16(unsigned dst, const void* src) {
    asm volatile("cp.async.cg.shared.global [%0], [%1], 16;" :: "r"(dst), "l"(src));
}
static __device__ __forceinline__ void cp_commit() {
    asm volatile("cp.async.commit_group;");
}
static __device__ __forceinline__ void cp_wait_all() {
    asm volatile("cp.async.wait_group 0;");
}
static __device__ __forceinline__ void ldmA(unsigned addr, unsigned& r0, unsigned& r1,
                                            unsigned& r2, unsigned& r3) {
    asm volatile("ldmatrix.sync.aligned.m8n8.x4.shared.b16 {%0,%1,%2,%3}, [%4];"
                 : "=r"(r0), "=r"(r1), "=r"(r2), "=r"(r3) : "r"(addr));
}
static __device__ __forceinline__ void ldmB(unsigned addr, unsigned& r0, unsigned& r1) {
    asm volatile("ldmatrix.sync.aligned.m8n8.x2.shared.b16 {%0,%1}, [%2];"
                 : "=r"(r0), "=r"(r1) : "r"(addr));
}
static __device__ __forceinline__ void mma16816(float* d, const unsigned* a,
                                                const unsigned* b) {
    asm volatile(
        "mma.sync.aligned.m16n8k16.row.col.f32.f16.f16.f32 "
        "{%0,%1,%2,%3}, {%4,%5,%6,%7}, {%8,%9}, {%0,%1,%2,%3};"
        : "+f"(d[0]), "+f"(d[1]), "+f"(d[2]), "+f"(d[3])
        : "r"(a[0]), "r"(a[1]), "r"(a[2]), "r"(a[3]), "r"(b[0]), "r"(b[1]));
}

// Fast branch-free erf-GELU (A&S 7.1.26, |eps_erf| < 1.5e-7)
static __device__ __forceinline__ float gelu_erf(float v) {
    float z = fabsf(v) * 0.70710678118654752440f;
    float t = __fdividef(1.0f, fmaf(0.3275911f, z, 1.0f));
    float p = fmaf(1.061405429f, t, -1.453152027f);
    p = fmaf(p, t, 1.421413741f);
    p = fmaf(p, t, -0.284496736f);
    p = fmaf(p, t, 0.254829592f);
    p *= t;
    float e = __expf(-z * z);
    float erfz = fmaf(-p, e, 1.0f);          // erf(|v|/sqrt2)
    float erfv = copysignf(erfz, v);
    return 0.5f * v * (1.0f + erfv);
}

// Per-mode recurrence params: w = exp(dt*A), c' = C*(w-1)/A
struct ModeParams {
    float ar[32], ai[32];       // log|w|, arg w
    float wr[32], wi[32];       // w
    float cr[32], ci[32];       // c'
};
static __device__ __forceinline__ void compute_params(
    ModeParams& P, int h, int n,
    const float* __restrict__ log_dt, const float* __restrict__ A_real,
    const float* __restrict__ A_imag, const float* __restrict__ C_real,
    const float* __restrict__ C_imag) {
    int idx = h * Nn + n;
    float dt = expf(log_dt[h]);
    float Ar = -expf(A_real[idx]);
    float Ai = A_imag[idx];
    float ar = Ar * dt, ai = Ai * dt;
    float er = expf(ar);
    float sn, cs;
    sincosf(ai, &sn, &cs);
    float wr = er * cs, wi = er * sn;
    float den = Ar * Ar + Ai * Ai;
    float e1r = wr - 1.0f, e1i = wi;
    float qr = (e1r * Ar + e1i * Ai) / den;
    float qi = (e1i * Ar - e1r * Ai) / den;
    float Cr = C_real[idx], Ci = C_imag[idx];
    P.ar[n] = ar; P.ai[n] = ai;
    P.wr[n] = wr; P.wi[n] = wi;
    P.cr[n] = Cr * qr - Ci * qi;
    P.ci[n] = Cr * qi + Ci * qr;
}

// =====================================================================
// k_transpose: u (b,l,h) fp32 -> g_V[h][bc][0..128) fp16
// cp.async into fp32 smem tile (chunk-XOR swizzled), convert on output.
// =====================================================================
__global__ void __launch_bounds__(256)
k_transpose(const float* __restrict__ u, int ht0) {
    int ht = blockIdx.x + ht0, c = blockIdx.y, b = blockIdx.z;
    __shared__ float ts32[128][36];   // [j][h-chunks swizzled], 144B rows
    unsigned tsA = smem_u32(ts32);
    int tid = threadIdx.x;

    const float* up = u + ((size_t)b * Ln + (size_t)c * Tn) * Hn + ht * 32;
    // 4 passes x 256 threads: row j = p*32 + (tid>>3), h-chunk ch = tid&7
    // phys chunk = ch ^ ((j>>3)&7)  -> conflict-free column read-back
    {
        int jr = tid >> 3, ch = tid & 7;
#pragma unroll
        for (int p = 0; p < 4; p++) {
            int j = p * 32 + jr;
            int phys = ch ^ ((j >> 3) & 7);
            cp16(tsA + (unsigned)((j * 36 + phys * 4) * 4),
                 up + (size_t)j * Hn + ch * 4);
        }
        cp_commit();
    }
    cp_wait_all();
    __syncthreads();

    // output: row = h (tid>>3), chm = m-chunk (tid&7); two uint4 per thread
    int row = tid >> 3;
    int chm = tid & 7;
    int bc = b * Cc + c;
    __half* dst = g_V + ((size_t)(ht * 32 + row) * BC + bc) * 128;
    int c0 = row >> 2, p0 = row & 3;
#pragma unroll
    for (int g = 0; g < 2; g++) {
        int mbase = (chm + g * 8) * 8;
        __half hv[8];
#pragma unroll
        for (int k = 0; k < 8; k++) {
            int j = mbase + k;
            int phys = c0 ^ ((j >> 3) & 7);
            hv[k] = __float2half(ts32[j][phys * 4 + p0]);
        }
        reinterpret_cast<uint4*>(dst)[chm + g * 8] =
            *reinterpret_cast<const uint4*>(hv);
    }
}

// =====================================================================
// k_fused: one block per (h, batch-half). Half = 4 sequences = 128 bc.
// (byte-identical to the 166.7us best)
// =====================================================================
#define LDB  200     // Bs row stride (halves)
#define LDA1 136     // Enc row stride
#define LDX  130     // Xl fp32 row stride
#define LDA2 200     // main A row stride
#define LDO  136     // epilogue staging stride
#define R1_OFF (128 * LDB)                    // halves
#define SMEM_FUSED ((128 * LDB) * 2 + 51200)  // bytes = 102400

__global__ void __launch_bounds__(256, 2)
k_fused(const float* __restrict__ log_dt, const float* __restrict__ A_real,
        const float* __restrict__ A_imag, const float* __restrict__ C_real,
        const float* __restrict__ C_imag, int h0) {
    int h = blockIdx.x + h0;
    int half = blockIdx.y;
    int tid = threadIdx.x;
    extern __shared__ __half sm[];
    __half* Bs = sm;                 // [128][LDB]
    __half* R1 = sm + R1_OFF;        // 51200B scratch: Enc / Xl / A / epilogue
    __shared__ ModeParams P;
    __shared__ float wTr[32], wTi[32], Ksh[Tn];

    // ---- phase 1: async u-tile (128 bc rows of this half) ----
    {
        const __half* vb = g_V + ((size_t)h * BC + half * 128) * 128;
        unsigned bsm = smem_u32(Bs);
        for (int i = tid; i < 128 * 16; i += 256) {
            int row = i >> 4, ch = i & 15;
            cp16(bsm + (unsigned)((row * LDB + ch * 8) * 2),
                 vb + (size_t)row * 128 + ch * 8);
        }
        cp_commit();
    }
    if (tid < 32) {
        compute_params(P, h, tid, log_dt, A_real, A_imag, C_real, C_imag);
        float erT = __expf(128.f * P.ar[tid]);
        float snT, csT;
        sincosf(128.f * P.ai[tid], &snT, &csT);
        wTr[tid] = erT * csT; wTi[tid] = erT * snT;
    }
    __syncthreads();

    int n = tid & 31, w16 = tid >> 5;
    float ar = P.ar[n], ai = P.ai[n];
    float wr = P.wr[n], wi = P.wi[n];
    float s0 = (float)(w16 * 16);
    float pBr, pBi;
    {
        float er = __expf(s0 * ar);
        float sn, cs;
        sincosf(s0 * ai, &sn, &cs);
        pBr = er * cs; pBi = er * sn;
    }

    // ---- phase 2a: inline Enc into R1 (chained) ----
    __half* EncS = R1;
    {
        float pr = pBr, pi = pBi;
#pragma unroll
        for (int q = 0; q < 16; q++) {
            int s = w16 * 16 + q;
            EncS[n * LDA1 + (127 - s)]        = __float2half(pr);
            EncS[(n + 32) * LDA1 + (127 - s)] = __float2half(pi);
            float nr = pr * wr - pi * wi;
            float ni = pr * wi + pi * wr;
            pr = nr; pi = ni;
        }
    }
    cp_wait_all();
    __syncthreads();

    int wid = tid >> 5, lane = tid & 31;
    int la = lane & 15;
    int aRowOff = (lane < 16) ? lane : (lane - 16);
    int aColOff = (lane < 16) ? 0 : 8;
    int bRowOff = la & 7;
    int bColOff = (la >> 3) * 8;

    // ---- phase 2b: encode GEMM  Xl[64,128] = Enc @ B_u^T (double-buffered) ----
    {
        int wm = wid & 1, wn = wid >> 1;
        int m_base = wm * 32, n_base = wn * 32;

        float acc[2][4][4];
#pragma unroll
        for (int a = 0; a < 2; a++)
#pragma unroll
            for (int bI = 0; bI < 4; bI++)
#pragma unroll
                for (int cI = 0; cI < 4; cI++) acc[a][bI][cI] = 0.f;

        unsigned eaB = smem_u32(&EncS[(m_base + aRowOff) * LDA1 + aColOff]);
        unsigned ebB = smem_u32(&Bs[(n_base + bRowOff) * LDB + bColOff]);
        unsigned af[2][2][4];
        unsigned bf[2][4][2];

#define LOAD_E(buf, ks_)                                                      \
    {                                                                         \
        const int kk_ = (ks_) * 16;                                           \
        _Pragma("unroll")                                                     \
        for (int mf = 0; mf < 2; mf++)                                        \
            ldmA(eaB + (unsigned)((mf * 16 * LDA1 + kk_) * 2),                \
                 af[buf][mf][0], af[buf][mf][1], af[buf][mf][2], af[buf][mf][3]); \
        _Pragma("unroll")                                                     \
        for (int nf = 0; nf < 4; nf++)                                        \
            ldmB(ebB + (unsigned)((nf * 8 * LDB + kk_) * 2),                  \
                 bf[buf][nf][0], bf[buf][nf][1]);                             \
    }
#define MMA_E(buf)                                                            \
    {                                                                         \
        _Pragma("unroll")                                                     \
        for (int mf = 0; mf < 2; mf++)                                        \
            _Pragma("unroll")                                                 \
            for (int nf = 0; nf < 4; nf++)                                    \
                mma16816(acc[mf][nf], af[buf][mf], bf[buf][nf]);              \
    }
        LOAD_E(0, 0)
#pragma unroll
        for (int it = 0; it < 8; it++) {
            int cur = it & 1;
            if (it < 7) LOAD_E(cur ^ 1, it + 1)
            MMA_E(cur)
        }
#undef LOAD_E
#undef MMA_E
        __syncthreads();   // Enc reads done -> reuse R1 as Xl

        float* Xls = reinterpret_cast<float*>(R1);
        int r = lane >> 2, cp = lane & 3;
#pragma unroll
        for (int mf = 0; mf < 2; mf++) {
#pragma unroll
            for (int nf = 0; nf < 4; nf++) {
                int m = m_base + mf * 16 + r;
                int nn = n_base + nf * 8 + cp * 2;
                *reinterpret_cast<float2*>(&Xls[m * LDX + nn]) =
                    make_float2(acc[mf][nf][0], acc[mf][nf][1]);
                *reinterpret_cast<float2*>(&Xls[(m + 8) * LDX + nn]) =
                    make_float2(acc[mf][nf][2], acc[mf][nf][3]);
            }
        }
    }
    __syncthreads();

    // ---- phase 3: combine (4 sequences) -> fp16 states into Bs [128..192) ----
    if (tid < 128) {
        const float* Xls = reinterpret_cast<const float*>(R1);
        int bl = tid >> 5;      // local batch 0..3
        float wtr = wTr[n], wti = wTi[n];
        float XR = 0.f, XI = 0.f;
        const float* xR = &Xls[n * LDX];
        const float* xI = &Xls[(n + 32) * LDX];
#pragma unroll 4
        for (int c = 0; c < Cc; c++) {
            int bc = bl * Cc + c;             // local row 0..127
            Bs[bc * LDB + 128 + n] = __float2half(XR);
            Bs[bc * LDB + 160 + n] = __float2half(XI);
            float lr = xR[bc], li = xI[bc];
            float nR = wtr * XR - wti * XI + lr;
            float nI = wtr * XI + wti * XR + li;
            XR = nR; XI = nI;
        }
    }
    __syncthreads();   // Xl reads done -> reuse R1 as A panel

    // ---- phase 4a: inline A panel (Dec + Ks chained, then Toeplitz) ----
    __half* As = R1;
    {
        float cr = P.cr[n], ci = P.ci[n];
        float tr = cr * pBr - ci * pBi;
        float ti = cr * pBi + ci * pBr;
#pragma unroll
        for (int q = 0; q < 16; q++) {
            int sp = w16 * 16 + q;
            float dr = tr * wr - ti * wi;
            float di = tr * wi + ti * wr;               // c' w^{sp+1}
            As[sp * LDA2 + 128 + n] = __float2half(2.0f * dr);
            As[sp * LDA2 + 160 + n] = __float2half(-2.0f * di);
            float term = 2.0f * tr;
#pragma unroll
            for (int off = 16; off; off >>= 1)
                term += __shfl_xor_sync(0xffffffffu, term, off);
            if (n == 0) Ksh[sp] = term;
            tr = dr; ti = di;
        }
    }
    __syncthreads();
    for (int i = tid; i < 128 * 16; i += 256) {
        int row = i >> 4, ch = i & 15;
        int j0 = ch * 8;
        __half hv[8];
#pragma unroll
        for (int k = 0; k < 8; k++) {
            int j = j0 + k;
            hv[k] = __float2half((row >= j) ? Ksh[row - j] : 0.f);
        }
        *reinterpret_cast<uint4*>(&As[row * LDA2 + j0]) =
            *reinterpret_cast<const uint4*>(hv);
    }
    __syncthreads();

    // ---- phase 4b: main GEMM  Y[128,128] = [Toep|Dec] @ B^T ----
    int wm = wid >> 2, wn2 = wid & 3;
    int m_base = wm * 64, n_base = wn2 * 32;
    unsigned aBase = smem_u32(&As[(m_base + aRowOff) * LDA2 + aColOff]);
    unsigned bBase = smem_u32(&Bs[(n_base + bRowOff) * LDB + bColOff]);

    float acc[4][4][4];
#pragma unroll
    for (int a = 0; a < 4; a++)
#pragma unroll
        for (int bI = 0; bI < 4; bI++)
#pragma unroll
            for (int cI = 0; cI < 4; cI++) acc[a][bI][cI] = 0.f;

    unsigned af[2][4][4];
    unsigned bf[2][4][2];

#define LOAD_AB(buf, ks_)                                                     \
    {                                                                         \
        const int kk_ = (ks_) * 16;                                           \
        _Pragma("unroll")                                                     \
        for (int mf = 0; mf < 4; mf++)                                        \
            ldmA(aBase + (unsigned)((mf * 16 * LDA2 + kk_) * 2),              \
                 af[buf][mf][0], af[buf][mf][1], af[buf][mf][2], af[buf][mf][3]); \
        _Pragma("unroll")                                                     \
        for (int nf = 0; nf < 4; nf++)                                        \
            ldmB(bBase + (unsigned)((nf * 8 * LDB + kk_) * 2),                \
                 bf[buf][nf][0], bf[buf][nf][1]);                             \
    }
#define MMA_STEP(buf)                                                         \
    {                                                                         \
        _Pragma("unroll")                                                     \
        for (int mf = 0; mf < 4; mf++)                                        \
            _Pragma("unroll")                                                 \
            for (int nf = 0; nf < 4; nf++)                                    \
                mma16816(acc[mf][nf], af[buf][mf], bf[buf][nf]);              \
    }

    if (wm == 0) {
        LOAD_AB(0, 0)
#pragma unroll
        for (int it = 0; it < 8; it++) {
            int cur = it & 1;
            if (it < 7) {
                int nks = (it + 1 < 4) ? (it + 1) : (it + 5);
                LOAD_AB(cur ^ 1, nks)
            }
            MMA_STEP(cur)
        }
    } else {
        LOAD_AB(0, 0)
#pragma unroll
        for (int it = 0; it < 12; it++) {
            int cur = it & 1;
            if (it < 11) LOAD_AB(cur ^ 1, it + 1)
            MMA_STEP(cur)
        }
    }
#undef LOAD_AB
#undef MMA_STEP

    // ---- phase 5: epilogue -> stage fp16 in R1, coalesced global store ----
    __syncthreads();
    __half* ot = R1;   // [128 bc][LDO]
    {
        int r = lane >> 2, cp = lane & 3;
#pragma unroll
        for (int mf = 0; mf < 4; mf++) {
            int m = m_base + mf * 16 + r;
#pragma unroll
            for (int nf = 0; nf < 4; nf++) {
                int nn = n_base + nf * 8 + cp * 2;
                ot[nn * LDO + m]           = __float2half(acc[mf][nf][0]);
                ot[(nn + 1) * LDO + m]     = __float2half(acc[mf][nf][1]);
                ot[nn * LDO + m + 8]       = __float2half(acc[mf][nf][2]);
                ot[(nn + 1) * LDO + m + 8] = __float2half(acc[mf][nf][3]);
            }
        }
    }
    __syncthreads();
    {
        __half* dst = g_yT16 + ((size_t)h * BC + half * 128) * Tn;
        for (int i = tid; i < 128 * 16; i += 256) {
            int row = i >> 4, ch = i & 15;
            *reinterpret_cast<uint4*>(&dst[row * Tn + ch * 8]) =
                *reinterpret_cast<const uint4*>(&ot[row * LDO + ch * 8]);
        }
    }
}

// =====================================================================
// k_final: yT16 -> out (b,l,h) + GELU. fp32 smem staging via
// __half22float2/float2 stores, float2-chunk XOR swizzle on rows.
// =====================================================================
__global__ void __launch_bounds__(256)
k_final(const float* __restrict__ u, const float* __restrict__ Dp,
        float* __restrict__ out, int ht0) {
    int ht = blockIdx.x + ht0, c = blockIdx.y, b = blockIdx.z;
    __shared__ float ys[32][132];   // [h row][i], float2-chunk swizzled
    int bc = b * Cc + c;

    {
#pragma unroll
        for (int qq = 0; qq < 2; qq++) {
            int idx = threadIdx.x + qq * 256;
            int row = idx >> 4;                    // h in tile
            int ch = idx & 15;                     // uint4 chunk (8 halves)
            const uint4* src = reinterpret_cast<const uint4*>(
                g_yT16 + ((size_t)(ht * 32 + row) * BC + bc) * Tn);
            uint4 v = src[ch];
            const __half2* hp = reinterpret_cast<const __half2*>(&v);
            int key = (row >> 3) * 2;
#pragma unroll
            for (int k = 0; k < 4; k++) {
                float2 f = __half22float2(hp[k]);
                int i = ch * 8 + k * 2;
                int cf = (i >> 1) ^ key;
                *reinterpret_cast<float2*>(&ys[row][cf * 2]) = f;
            }
        }
    }
    __syncthreads();

    float Dv = *Dp;
    int lane = threadIdx.x & 31;
    int r = threadIdx.x >> 5;
    int key = (lane >> 3) * 2;
    size_t base = ((size_t)b * Ln + (size_t)c * Tn + r) * Hn + ht * 32 + lane;
    if (Dv != 0.0f) {
#pragma unroll
        for (int i0 = 0; i0 < Tn; i0 += 8) {
            int i = i0 + r;
            int cf = (i >> 1) ^ key;
            float v = ys[lane][cf * 2 + (i & 1)];
            size_t gidx = base + (size_t)i0 * Hn;
            out[gidx] = gelu_erf(v + Dv * u[gidx]);
        }
    } else {
#pragma unroll
        for (int i0 = 0; i0 < Tn; i0 += 8) {
            int i = i0 + r;
            int cf = (i >> 1) ^ key;
            float v = ys[lane][cf * 2 + (i & 1)];
            size_t gidx = base + (size_t)i0 * Hn;
            out[gidx] = gelu_erf(v);
        }
    }
}

// =====================================================================
// launch: two staggered h-half pipelines on two streams (fork/join)
// =====================================================================
extern "C" void kernel_launch(void* const* d_in, const int* in_sizes, int n_in,
                              void* d_out, int out_size) {
    (void)in_sizes; (void)n_in; (void)out_size;
    const float* u      = (const float*)d_in[0];
    const float* log_dt = (const float*)d_in[1];
    const float* A_real = (const float*)d_in[2];
    const float* A_imag = (const float*)d_in[3];
    const float* C_real = (const float*)d_in[4];
    const float* C_imag = (const float*)d_in[5];
    const float* D      = (const float*)d_in[6];
    float* out = (float*)d_out;

    static bool init_done = false;
    static cudaStream_t s2;
    static cudaEvent_t evT, evJoin;
    if (!init_done) {
        cudaFuncSetAttribute(k_fused, cudaFuncAttributeMaxDynamicSharedMemorySize,
                             SMEM_FUSED);
        cudaStreamCreateWithFlags(&s2, cudaStreamNonBlocking);
        cudaEventCreateWithFlags(&evT, cudaEventDisableTiming);
        cudaEventCreateWithFlags(&evJoin, cudaEventDisableTiming);
        init_done = true;
    }

    // Pipeline A (h 0..511) on the launch stream
    k_transpose<<<dim3(16, Cc, Bn), 256>>>(u, 0);
    cudaEventRecord(evT, 0);
    k_fused<<<dim3(512, 2), 256, SMEM_FUSED>>>(log_dt, A_real, A_imag,
                                               C_real, C_imag, 0);
    k_final<<<dim3(16, Cc, Bn), 256>>>(u, D, out, 0);

    // Pipeline B (h 512..1023) on s2, staggered after T_A
    cudaStreamWaitEvent(s2, evT, 0);
    k_transpose<<<dim3(16, Cc, Bn), 256, 0, s2>>>(u, 16);
    k_fused<<<dim3(512, 2), 256, SMEM_FUSED, s2>>>(log_dt, A_real, A_imag,
                                                   C_real, C_imag, 512);
    k_final<<<dim3(16, Cc, Bn), 256, 0, s2>>>(u, D, out, 16);

    // join back to the launch stream
    cudaEventRecord(evJoin, s2);
    cudaStreamWaitEvent(0, evJoin, 0);
}